// round 11
// baseline (speedup 1.0000x reference)
#include <cuda_runtime.h>
#include <cuda_fp16.h>
#include <cstdint>

#define NTOK  4096
#define HID   1024
#define NEXP  16
#define IDIM  2048
#define CAP   768
#define NFLAT (NTOK * 2)

// ---------------- device scratch (no allocs allowed) ----------------
__device__ int   g_flat_sel[NFLAT];
__device__ float g_flat_scale[NFLAT];
__device__ int   g_assign_pos[NFLAT];
__device__ int   g_expert_count[NEXP];
__device__ int   g_expert_tok[NEXP * CAP];

__device__ __align__(256) __half g_x1[(size_t)NEXP * CAP * HID];          // A1 fp16
__device__ __align__(256) __half g_i2[(size_t)NEXP * CAP * IDIM];         // A2 fp16
__device__ __align__(256) __half g_w31[(size_t)NEXP * 2 * IDIM * HID];    // B1 fp16
__device__ __align__(256) __half g_w2[(size_t)NEXP * HID * IDIM];         // B2 fp16
__device__ __align__(256) float g_hbuf[(size_t)NEXP * CAP * 2 * IDIM];
__device__ __align__(256) float g_ybuf[(size_t)NEXP * CAP * HID];

// ---------------- helpers ----------------
__device__ __forceinline__ uint32_t smem_u32(const void* p) {
    uint32_t a;
    asm("{ .reg .u64 t; cvta.to.shared.u64 t, %1; cvt.u32.u64 %0, t; }" : "=r"(a) : "l"(p));
    return a;
}
__device__ __forceinline__ void cpa16(uint32_t s, const void* g) {
    asm volatile("cp.async.cg.shared.global [%0], [%1], 16;" :: "r"(s), "l"(g) : "memory");
}
__device__ __forceinline__ void ldsm4(uint32_t& r0, uint32_t& r1, uint32_t& r2, uint32_t& r3,
                                      uint32_t addr) {
    asm volatile("ldmatrix.sync.aligned.m8n8.x4.shared.b16 {%0,%1,%2,%3}, [%4];"
                 : "=r"(r0), "=r"(r1), "=r"(r2), "=r"(r3) : "r"(addr));
}
__device__ __forceinline__ void mma16816(float* c, const uint32_t* a, const uint32_t* b) {
    asm volatile(
        "mma.sync.aligned.m16n8k16.row.col.f32.f16.f16.f32 "
        "{%0,%1,%2,%3}, {%4,%5,%6,%7}, {%8,%9}, {%0,%1,%2,%3};"
        : "+f"(c[0]), "+f"(c[1]), "+f"(c[2]), "+f"(c[3])
        : "r"(a[0]), "r"(a[1]), "r"(a[2]), "r"(a[3]), "r"(b[0]), "r"(b[1]));
}
__device__ __forceinline__ uint32_t pack2h(__half a, __half b) {
    __half2 t(a, b);
    return *reinterpret_cast<uint32_t*>(&t);
}
// padded smem tiles: rows x 32 fp16 (64B data), row stride 80B -> conflict-free
#define ROW_B 80
#define TILE_A_B (128 * ROW_B)            // 10240
#define TILE_B_B (256 * ROW_B)            // 20480
#define STAGE_B (TILE_A_B + TILE_B_B)     // 30720
#define NSTAGE 3
#define SMEM_BYTES (NSTAGE * STAGE_B)     // 92160

// ---------------- routing: softmax top-2 + capacity positions ----------------
__global__ void routing_kernel(const float* __restrict__ logits) {
    __shared__ unsigned char sh_sel[NFLAT];
    const int tid = threadIdx.x;  // 512 threads = 16 warps

    for (int t = tid; t < NTOK; t += 512) {
        const float* l = logits + t * NEXP;
        float l1 = -1e30f, l2 = -1e30f;
        int i1 = 0, i2 = 0;
#pragma unroll
        for (int j = 0; j < NEXP; j++) {
            float v = l[j];
            if (v > l1)      { l2 = l1; i2 = i1; l1 = v; i1 = j; }
            else if (v > l2) { l2 = v; i2 = j; }
        }
        float e2 = __expf(l2 - l1);
        float s1 = 1.f / (1.f + e2);
        g_flat_sel[2 * t]     = i1;
        g_flat_sel[2 * t + 1] = i2;
        g_flat_scale[2 * t]     = s1;
        g_flat_scale[2 * t + 1] = 1.f - s1;
        sh_sel[2 * t]     = (unsigned char)i1;
        sh_sel[2 * t + 1] = (unsigned char)i2;
    }
    __syncthreads();

    const int w = tid >> 5, lane = tid & 31;
    int base = 0;
    for (int c = 0; c < NFLAT; c += 32) {
        int s = sh_sel[c + lane];
        unsigned m = __ballot_sync(0xffffffffu, s == w);
        if (s == w) {
            int pos = base + __popc(m & ((1u << lane) - 1u));
            g_assign_pos[c + lane] = (pos < CAP) ? pos : -1;
            if (pos < CAP) g_expert_tok[w * CAP + pos] = (c + lane) >> 1;
        }
        base += __popc(m);
    }
    if (lane == 0) g_expert_count[w] = base < CAP ? base : CAP;
}

// ---------------- weight convert: f32 -> fp16 ----------------
// Destination __device__ arrays resolved in DEVICE code (host symbol = R4-R6 bug).
__global__ void wcvt_kernel(const float* __restrict__ src, int which, int n4) {
    __half* dst = which ? g_w2 : g_w31;
    int stride = gridDim.x * blockDim.x;
    for (int i = blockIdx.x * blockDim.x + threadIdx.x; i < n4; i += stride) {
        float4 v = ((const float4*)src)[i];
        ((uint2*)dst)[i] = make_uint2(
            pack2h(__float2half_rn(v.x), __float2half_rn(v.y)),
            pack2h(__float2half_rn(v.z), __float2half_rn(v.w)));
    }
}

// ---------------- gather rows into contiguous fp16 buffer ----------------
__global__ void gather_kernel(const float* __restrict__ hidden) {
    const int row = blockIdx.x;            // [0, NEXP*CAP)
    const int e = row / CAP, p = row % CAP;
    const int t = threadIdx.x;             // 256, one float4 each
    float4 v = make_float4(0.f, 0.f, 0.f, 0.f);
    if (p < g_expert_count[e]) {
        int tok = g_expert_tok[row];
        v = ((const float4*)(hidden + (size_t)tok * HID))[t];
    }
    *(uint2*)(g_x1 + (size_t)row * HID + t * 4) = make_uint2(
        pack2h(__float2half_rn(v.x), __float2half_rn(v.y)),
        pack2h(__float2half_rn(v.z), __float2half_rn(v.w)));
}

// ---------------- fp16 HMMA GEMM: C[row][n] = sum_k A[row][k] * B[n][k] ----------------
// CTA tile 128x256, warp tile 64x64 (2m x 4n warps), BK=32, 3-stage cp.async.
template<int NTOT, int K, bool FIRST>
__global__ __launch_bounds__(256, 1) void hmma_gemm() {
    const int e = blockIdx.z;
    if ((int)(blockIdx.y * 128) >= g_expert_count[e]) return;

    extern __shared__ __align__(128) char smem[];
    const uint32_t sb = smem_u32(smem);

    const __half* A = (FIRST ? g_x1 : g_i2)
        + ((size_t)e * CAP + (size_t)blockIdx.y * 128) * K;
    const __half* B = (FIRST ? g_w31 : g_w2)
        + ((size_t)e * NTOT + (size_t)blockIdx.x * 256) * K;
    float* C = (FIRST ? g_hbuf : g_ybuf)
        + ((size_t)e * CAP + (size_t)blockIdx.y * 128) * NTOT + (size_t)blockIdx.x * 256;

    const int tid = threadIdx.x, lane = tid & 31, warp = tid >> 5;
    const int wm = (warp & 1) * 64, wn = (warp >> 1) * 64;

    // cp.async load map: A rows (tid>>2)+{0,64}; B rows (tid>>2)+{0,64,128,192}; chunk tid&3
    const int lr = tid >> 2, lc = tid & 3;
    const uint32_t sA0 = (uint32_t)(lr * ROW_B + lc * 16);
    const uint32_t sA1 = sA0 + 64 * ROW_B;
    const size_t gA0 = (size_t)lr * K + lc * 8;
    const size_t gStep = (size_t)64 * K;

    // ldmatrix per-lane offsets (verified coordinates from R7-R10)
    uint32_t aoff[4][2], boff[4][2];
    {
        const int am = lane & 15, ah = lane >> 4;
        const int mt = lane >> 3;
        const int bn = ((mt >> 1) << 3) + (lane & 7), bh = mt & 1;
#pragma unroll
        for (int i = 0; i < 4; i++)
#pragma unroll
            for (int kk = 0; kk < 2; kk++)
                aoff[i][kk] = (uint32_t)((wm + i * 16 + am) * ROW_B + (kk * 2 + ah) * 16);
#pragma unroll
        for (int j = 0; j < 4; j++)
#pragma unroll
            for (int kk = 0; kk < 2; kk++)
                boff[j][kk] = (uint32_t)((wn + j * 16 + bn) * ROW_B + (kk * 2 + bh) * 16);
    }

    float acc[4][8][4];
#pragma unroll
    for (int i = 0; i < 4; i++)
#pragma unroll
        for (int j = 0; j < 8; j++)
#pragma unroll
            for (int q = 0; q < 4; q++) acc[i][j][q] = 0.f;

    constexpr int NK = K / 32;

    auto load_stage = [&](int kt) {
        const int kl = kt * 32;
        const uint32_t sa = sb + (kt % NSTAGE) * STAGE_B;
        const uint32_t sbf = sa + TILE_A_B;
        cpa16(sa + sA0, A + gA0 + kl);
        cpa16(sa + sA1, A + gA0 + gStep + kl);
#pragma unroll
        for (int r = 0; r < 4; r++)
            cpa16(sbf + sA0 + r * 64 * ROW_B, B + gA0 + r * gStep + kl);
    };

    load_stage(0);
    asm volatile("cp.async.commit_group;" ::: "memory");
    load_stage(1);
    asm volatile("cp.async.commit_group;" ::: "memory");

    for (int kt = 0; kt < NK; kt++) {
        asm volatile("cp.async.wait_group 1;" ::: "memory");
        __syncthreads();
        if (kt + 2 < NK) load_stage(kt + 2);
        asm volatile("cp.async.commit_group;" ::: "memory");

        const uint32_t sa = sb + (kt % NSTAGE) * STAGE_B, sbf = sa + TILE_A_B;
#pragma unroll
        for (int kk = 0; kk < 2; kk++) {
            uint32_t aF[4][4], bF[8][2];
#pragma unroll
            for (int i = 0; i < 4; i++)
                ldsm4(aF[i][0], aF[i][1], aF[i][2], aF[i][3], sa + aoff[i][kk]);
#pragma unroll
            for (int j = 0; j < 4; j++)
                ldsm4(bF[2 * j][0], bF[2 * j][1], bF[2 * j + 1][0], bF[2 * j + 1][1],
                      sbf + boff[j][kk]);
#pragma unroll
            for (int i = 0; i < 4; i++)
#pragma unroll
                for (int j = 0; j < 8; j++)
                    mma16816(acc[i][j], aF[i], bF[j]);
        }
    }

    // epilogue: standard m16n8 C layout, f32 stores
    const int er = lane >> 2, ec = (lane & 3) * 2;
#pragma unroll
    for (int i = 0; i < 4; i++) {
#pragma unroll
        for (int j = 0; j < 8; j++) {
            float* p0 = C + (size_t)(wm + i * 16 + er) * NTOT + wn + j * 8 + ec;
            float* p1 = p0 + (size_t)8 * NTOT;
            *(float2*)p0 = make_float2(acc[i][j][0], acc[i][j][1]);
            *(float2*)p1 = make_float2(acc[i][j][2], acc[i][j][3]);
        }
    }
}

// ---------------- activation: inter = g3 * silu(g1) -> fp16 ----------------
__global__ void act_kernel() {
    size_t idx4 = (size_t)blockIdx.x * 256 + threadIdx.x;   // float4 groups
    size_t row = idx4 >> 9;            // IDIM/4 = 512 groups per row
    int c4 = (int)(idx4 & 511);
    const float* hrow = g_hbuf + row * (2 * IDIM);
    float4 g3 = *(const float4*)(hrow + c4 * 4);
    float4 g1 = *(const float4*)(hrow + IDIM + c4 * 4);
    float4 o;
    o.x = g3.x * (g1.x / (1.f + __expf(-g1.x)));
    o.y = g3.y * (g1.y / (1.f + __expf(-g1.y)));
    o.z = g3.z * (g1.z / (1.f + __expf(-g1.z)));
    o.w = g3.w * (g1.w / (1.f + __expf(-g1.w)));
    *(uint2*)(g_i2 + row * IDIM + c4 * 4) = make_uint2(
        pack2h(__float2half_rn(o.x), __float2half_rn(o.y)),
        pack2h(__float2half_rn(o.z), __float2half_rn(o.w)));
}

// ---------------- scatter back: out[t] = sum_k scale * y[e, pos] ----------------
__global__ void scatter_kernel(float* __restrict__ out) {
    const int t = blockIdx.x;
    const int tid = threadIdx.x;  // 256, one float4 each
    float4 acc = make_float4(0.f, 0.f, 0.f, 0.f);
#pragma unroll
    for (int k = 0; k < 2; k++) {
        int f = 2 * t + k;
        int pos = g_assign_pos[f];
        if (pos >= 0) {
            int e = g_flat_sel[f];
            float s = g_flat_scale[f];
            float4 v = ((const float4*)(g_ybuf + (size_t)(e * CAP + pos) * HID))[tid];
            acc.x += s * v.x; acc.y += s * v.y; acc.z += s * v.z; acc.w += s * v.w;
        }
    }
    ((float4*)(out + (size_t)t * HID))[tid] = acc;
}

// ---------------- launch ----------------
extern "C" void kernel_launch(void* const* d_in, const int* in_sizes, int n_in,
                              void* d_out, int out_size) {
    const float* hidden = (const float*)d_in[0];
    const float* logits = (const float*)d_in[1];
    const float* w31    = (const float*)d_in[2];
    const float* w2     = (const float*)d_in[3];
    float* out = (float*)d_out;

    static int smem_set = 0;
    if (!smem_set) {
        cudaFuncSetAttribute(hmma_gemm<2 * IDIM, HID, true>,
                             cudaFuncAttributeMaxDynamicSharedMemorySize, SMEM_BYTES);
        cudaFuncSetAttribute(hmma_gemm<HID, IDIM, false>,
                             cudaFuncAttributeMaxDynamicSharedMemorySize, SMEM_BYTES);
        smem_set = 1;
    }

    routing_kernel<<<1, 512>>>(logits);
    gather_kernel<<<NEXP * CAP, 256>>>(hidden);
    wcvt_kernel<<<4096, 256>>>(w31, 0, NEXP * 2 * IDIM * HID / 4);
    wcvt_kernel<<<4096, 256>>>(w2, 1, NEXP * HID * IDIM / 4);
    hmma_gemm<2 * IDIM, HID, true><<<dim3(16, 6, NEXP), 256, SMEM_BYTES>>>();
    act_kernel<<<(NEXP * CAP * IDIM / 4) / 256, 256>>>();
    hmma_gemm<HID, IDIM, false><<<dim3(4, 6, NEXP), 256, SMEM_BYTES>>>();
    scatter_kernel<<<NTOK, 256>>>(out);
}

// round 12
// speedup vs baseline: 1.1127x; 1.1127x over previous
#include <cuda_runtime.h>
#include <cuda_fp16.h>
#include <cstdint>

#define NTOK  4096
#define HID   1024
#define NEXP  16
#define IDIM  2048
#define CAP   768
#define NFLAT (NTOK * 2)

// ---------------- device scratch (no allocs allowed) ----------------
__device__ int   g_flat_sel[NFLAT];
__device__ float g_flat_scale[NFLAT];
__device__ int   g_assign_pos[NFLAT];
__device__ int   g_expert_count[NEXP];
__device__ int   g_expert_tok[NEXP * CAP];

__device__ __align__(256) __half g_x1[(size_t)NEXP * CAP * HID];          // A1 fp16
__device__ __align__(256) __half g_i2[(size_t)NEXP * CAP * IDIM];         // inter fp16
__device__ __align__(256) __half g_w31[(size_t)NEXP * 2 * IDIM * HID];    // B1 fp16
__device__ __align__(256) __half g_w2[(size_t)NEXP * HID * IDIM];         // B2 fp16
__device__ __align__(256) float g_ybuf[(size_t)NEXP * CAP * HID];

// ---------------- helpers ----------------
__device__ __forceinline__ uint32_t smem_u32(const void* p) {
    uint32_t a;
    asm("{ .reg .u64 t; cvta.to.shared.u64 t, %1; cvt.u32.u64 %0, t; }" : "=r"(a) : "l"(p));
    return a;
}
__device__ __forceinline__ void cpa16(uint32_t s, const void* g) {
    asm volatile("cp.async.cg.shared.global [%0], [%1], 16;" :: "r"(s), "l"(g) : "memory");
}
__device__ __forceinline__ void ldsm4(uint32_t& r0, uint32_t& r1, uint32_t& r2, uint32_t& r3,
                                      uint32_t addr) {
    asm volatile("ldmatrix.sync.aligned.m8n8.x4.shared.b16 {%0,%1,%2,%3}, [%4];"
                 : "=r"(r0), "=r"(r1), "=r"(r2), "=r"(r3) : "r"(addr));
}
__device__ __forceinline__ void mma16816(float* c, const uint32_t* a, const uint32_t* b) {
    asm volatile(
        "mma.sync.aligned.m16n8k16.row.col.f32.f16.f16.f32 "
        "{%0,%1,%2,%3}, {%4,%5,%6,%7}, {%8,%9}, {%0,%1,%2,%3};"
        : "+f"(c[0]), "+f"(c[1]), "+f"(c[2]), "+f"(c[3])
        : "r"(a[0]), "r"(a[1]), "r"(a[2]), "r"(a[3]), "r"(b[0]), "r"(b[1]));
}
__device__ __forceinline__ uint32_t pack2h(__half a, __half b) {
    __half2 t(a, b);
    return *reinterpret_cast<uint32_t*>(&t);
}
__device__ __forceinline__ float silu_f(float v) {
    return v / (1.f + __expf(-v));
}
// padded smem tiles: rows x 32 fp16 (64B data), row stride 80B -> conflict-free
#define ROW_B 80
#define TILE_128 (128 * ROW_B)            // 10240
#define TILE_256 (256 * ROW_B)            // 20480
// GEMM1 fused: A(128) + B(256: g3|g1)
#define STAGE1_B (TILE_128 + TILE_256)    // 30720
#define SMEM1 (3 * STAGE1_B)              // 92160
// GEMM2: A(128) + B(128)
#define STAGE2_B (2 * TILE_128)           // 20480
#define SMEM2 (3 * STAGE2_B)              // 61440

// ---------------- routing: softmax top-2 + capacity positions ----------------
__global__ void routing_kernel(const float* __restrict__ logits) {
    __shared__ unsigned char sh_sel[NFLAT];
    const int tid = threadIdx.x;  // 512 threads = 16 warps

    for (int t = tid; t < NTOK; t += 512) {
        const float* l = logits + t * NEXP;
        float l1 = -1e30f, l2 = -1e30f;
        int i1 = 0, i2 = 0;
#pragma unroll
        for (int j = 0; j < NEXP; j++) {
            float v = l[j];
            if (v > l1)      { l2 = l1; i2 = i1; l1 = v; i1 = j; }
            else if (v > l2) { l2 = v; i2 = j; }
        }
        float e2 = __expf(l2 - l1);
        float s1 = 1.f / (1.f + e2);
        g_flat_sel[2 * t]     = i1;
        g_flat_sel[2 * t + 1] = i2;
        g_flat_scale[2 * t]     = s1;
        g_flat_scale[2 * t + 1] = 1.f - s1;
        sh_sel[2 * t]     = (unsigned char)i1;
        sh_sel[2 * t + 1] = (unsigned char)i2;
    }
    __syncthreads();

    const int w = tid >> 5, lane = tid & 31;
    int base = 0;
    for (int c = 0; c < NFLAT; c += 32) {
        int s = sh_sel[c + lane];
        unsigned m = __ballot_sync(0xffffffffu, s == w);
        if (s == w) {
            int pos = base + __popc(m & ((1u << lane) - 1u));
            g_assign_pos[c + lane] = (pos < CAP) ? pos : -1;
            if (pos < CAP) g_expert_tok[w * CAP + pos] = (c + lane) >> 1;
        }
        base += __popc(m);
    }
    if (lane == 0) g_expert_count[w] = base < CAP ? base : CAP;
}

// ---------------- weight convert: f32 -> fp16 (device-resolved dst) ----------------
__global__ void wcvt_kernel(const float* __restrict__ src, int which, int n4) {
    __half* dst = which ? g_w2 : g_w31;
    int stride = gridDim.x * blockDim.x;
    for (int i = blockIdx.x * blockDim.x + threadIdx.x; i < n4; i += stride) {
        float4 v = ((const float4*)src)[i];
        ((uint2*)dst)[i] = make_uint2(
            pack2h(__float2half_rn(v.x), __float2half_rn(v.y)),
            pack2h(__float2half_rn(v.z), __float2half_rn(v.w)));
    }
}

// ---------------- gather rows into contiguous fp16 buffer ----------------
__global__ void gather_kernel(const float* __restrict__ hidden) {
    const int row = blockIdx.x;            // [0, NEXP*CAP)
    const int e = row / CAP, p = row % CAP;
    const int t = threadIdx.x;             // 256, one float4 each
    float4 v = make_float4(0.f, 0.f, 0.f, 0.f);
    if (p < g_expert_count[e]) {
        int tok = g_expert_tok[row];
        v = ((const float4*)(hidden + (size_t)tok * HID))[t];
    }
    *(uint2*)(g_x1 + (size_t)row * HID + t * 4) = make_uint2(
        pack2h(__float2half_rn(v.x), __float2half_rn(v.y)),
        pack2h(__float2half_rn(v.z), __float2half_rn(v.w)));
}

// ---------------- fused GEMM1 + SiLU: inter = (x@g3^T) * silu(x@g1^T) -> fp16 ----------------
// CTA: 512 threads (16 warps, 4m x 4n), tile 128 rows x 128 inter-cols; B smem holds
// the g3 rows AND the matching g1 rows (256 smem rows). Warp tile 32x32 per half.
__global__ __launch_bounds__(512, 1) void gemm1_fused() {
    const int e = blockIdx.z;
    if ((int)(blockIdx.y * 128) >= g_expert_count[e]) return;

    extern __shared__ __align__(128) char smem[];
    const uint32_t sb = smem_u32(smem);
    constexpr int K = HID;

    const size_t rowbase = (size_t)e * CAP + (size_t)blockIdx.y * 128;
    const __half* A  = g_x1 + rowbase * K;
    const __half* B3 = g_w31 + ((size_t)e * 2 * IDIM + (size_t)blockIdx.x * 128) * K;
    const __half* B1 = g_w31 + ((size_t)e * 2 * IDIM + IDIM + (size_t)blockIdx.x * 128) * K;

    const int tid = threadIdx.x, lane = tid & 31, warp = tid >> 5;
    const int wm = (warp & 3) * 32, wn = (warp >> 2) * 32;

    // loaders: A 1 chunk/thread (rows 0..127), B 2 chunks/thread (g3 row lr, g1 row lr)
    const int lr = tid >> 2, lc = tid & 3;
    const uint32_t sA = (uint32_t)(lr * ROW_B + lc * 16);
    const size_t gA = (size_t)lr * K + lc * 8;

    // ldmatrix per-lane offsets
    uint32_t aoff[2][2], b3off[2][2], b1off[2][2];
    {
        const int am = lane & 15, ah = lane >> 4;
        const int mt = lane >> 3;
        const int bn = ((mt >> 1) << 3) + (lane & 7), bh = mt & 1;
#pragma unroll
        for (int i = 0; i < 2; i++)
#pragma unroll
            for (int kk = 0; kk < 2; kk++)
                aoff[i][kk] = (uint32_t)((wm + i * 16 + am) * ROW_B + (kk * 2 + ah) * 16);
#pragma unroll
        for (int j = 0; j < 2; j++)
#pragma unroll
            for (int kk = 0; kk < 2; kk++) {
                b3off[j][kk] = (uint32_t)((wn + j * 16 + bn) * ROW_B + (kk * 2 + bh) * 16);
                b1off[j][kk] = b3off[j][kk] + (uint32_t)(128 * ROW_B);
            }
    }

    float acc3[2][4][4], acc1[2][4][4];
#pragma unroll
    for (int i = 0; i < 2; i++)
#pragma unroll
        for (int j = 0; j < 4; j++)
#pragma unroll
            for (int q = 0; q < 4; q++) { acc3[i][j][q] = 0.f; acc1[i][j][q] = 0.f; }

    constexpr int NK = K / 32;

    auto load_stage = [&](int kt) {
        const int kl = kt * 32;
        const uint32_t sa = sb + (kt % 3) * STAGE1_B;
        const uint32_t sbf = sa + TILE_128;
        cpa16(sa + sA, A + gA + kl);
        cpa16(sbf + sA, B3 + gA + kl);
        cpa16(sbf + (uint32_t)(128 * ROW_B) + sA, B1 + gA + kl);
    };

    load_stage(0);
    asm volatile("cp.async.commit_group;" ::: "memory");
    load_stage(1);
    asm volatile("cp.async.commit_group;" ::: "memory");

    for (int kt = 0; kt < NK; kt++) {
        asm volatile("cp.async.wait_group 1;" ::: "memory");
        __syncthreads();
        if (kt + 2 < NK) load_stage(kt + 2);
        asm volatile("cp.async.commit_group;" ::: "memory");

        const uint32_t sa = sb + (kt % 3) * STAGE1_B, sbf = sa + TILE_128;
#pragma unroll
        for (int kk = 0; kk < 2; kk++) {
            uint32_t aF[2][4], b3F[4][2], b1F[4][2];
            ldsm4(aF[0][0], aF[0][1], aF[0][2], aF[0][3], sa + aoff[0][kk]);
            ldsm4(aF[1][0], aF[1][1], aF[1][2], aF[1][3], sa + aoff[1][kk]);
#pragma unroll
            for (int j = 0; j < 2; j++) {
                ldsm4(b3F[2 * j][0], b3F[2 * j][1], b3F[2 * j + 1][0], b3F[2 * j + 1][1],
                      sbf + b3off[j][kk]);
                ldsm4(b1F[2 * j][0], b1F[2 * j][1], b1F[2 * j + 1][0], b1F[2 * j + 1][1],
                      sbf + b1off[j][kk]);
            }
#pragma unroll
            for (int i = 0; i < 2; i++)
#pragma unroll
                for (int j = 0; j < 4; j++) {
                    mma16816(acc3[i][j], aF[i], b3F[j]);
                    mma16816(acc1[i][j], aF[i], b1F[j]);
                }
        }
    }

    // fused epilogue: inter = acc3 * silu(acc1), write fp16 g_i2 directly
    const int er = lane >> 2, ec = (lane & 3) * 2;
#pragma unroll
    for (int i = 0; i < 2; i++) {
#pragma unroll
        for (int j = 0; j < 4; j++) {
            const int col = blockIdx.x * 128 + wn + j * 8 + ec;
            const size_t r0 = rowbase + wm + i * 16 + er;
            float v0 = acc3[i][j][0] * silu_f(acc1[i][j][0]);
            float v1 = acc3[i][j][1] * silu_f(acc1[i][j][1]);
            float v2 = acc3[i][j][2] * silu_f(acc1[i][j][2]);
            float v3 = acc3[i][j][3] * silu_f(acc1[i][j][3]);
            *(uint32_t*)(g_i2 + r0 * IDIM + col) =
                pack2h(__float2half_rn(v0), __float2half_rn(v1));
            *(uint32_t*)(g_i2 + (r0 + 8) * IDIM + col) =
                pack2h(__float2half_rn(v2), __float2half_rn(v3));
        }
    }
}

// ---------------- GEMM2 (R10 config): y = inter @ w2^T, f32 out ----------------
__global__ __launch_bounds__(256, 2) void gemm2_kernel() {
    const int e = blockIdx.z;
    if ((int)(blockIdx.y * 128) >= g_expert_count[e]) return;

    extern __shared__ __align__(128) char smem[];
    const uint32_t sb = smem_u32(smem);
    constexpr int K = IDIM;
    constexpr int NTOT = HID;

    const __half* A = g_i2 + ((size_t)e * CAP + (size_t)blockIdx.y * 128) * K;
    const __half* B = g_w2 + ((size_t)e * NTOT + (size_t)blockIdx.x * 128) * K;
    float* C = g_ybuf
        + ((size_t)e * CAP + (size_t)blockIdx.y * 128) * NTOT + (size_t)blockIdx.x * 128;

    const int tid = threadIdx.x, lane = tid & 31, warp = tid >> 5;
    const int wm = (warp & 3) * 32, wn = (warp >> 2) * 64;

    const int lrow0 = tid >> 2, lc0 = tid & 3;
    const int lrow1 = lrow0 + 64;
    const uint32_t s0 = (uint32_t)(lrow0 * ROW_B + lc0 * 16);
    const uint32_t s1 = (uint32_t)(lrow1 * ROW_B + lc0 * 16);
    const size_t ga0 = (size_t)lrow0 * K + lc0 * 8;
    const size_t ga1 = (size_t)lrow1 * K + lc0 * 8;

    uint32_t aoff[2][2], boff[4][2];
    {
        const int am = lane & 15, ah = lane >> 4;
        const int mt = lane >> 3;
        const int bn = ((mt >> 1) << 3) + (lane & 7), bh = mt & 1;
#pragma unroll
        for (int i = 0; i < 2; i++)
#pragma unroll
            for (int kk = 0; kk < 2; kk++)
                aoff[i][kk] = (uint32_t)((wm + i * 16 + am) * ROW_B + (kk * 2 + ah) * 16);
#pragma unroll
        for (int j = 0; j < 4; j++)
#pragma unroll
            for (int kk = 0; kk < 2; kk++)
                boff[j][kk] = (uint32_t)((wn + j * 16 + bn) * ROW_B + (kk * 2 + bh) * 16);
    }

    float acc[2][8][4];
#pragma unroll
    for (int i = 0; i < 2; i++)
#pragma unroll
        for (int j = 0; j < 8; j++)
#pragma unroll
            for (int q = 0; q < 4; q++) acc[i][j][q] = 0.f;

    constexpr int NK = K / 32;

    auto load_stage = [&](int kt) {
        const int kl = kt * 32;
        const uint32_t sa = sb + (kt % 3) * STAGE2_B;
        cpa16(sa + s0, A + ga0 + kl);
        cpa16(sa + s1, A + ga1 + kl);
        cpa16(sa + TILE_128 + s0, B + ga0 + kl);
        cpa16(sa + TILE_128 + s1, B + ga1 + kl);
    };

    load_stage(0);
    asm volatile("cp.async.commit_group;" ::: "memory");
    load_stage(1);
    asm volatile("cp.async.commit_group;" ::: "memory");

    for (int kt = 0; kt < NK; kt++) {
        asm volatile("cp.async.wait_group 1;" ::: "memory");
        __syncthreads();
        if (kt + 2 < NK) load_stage(kt + 2);
        asm volatile("cp.async.commit_group;" ::: "memory");

        const uint32_t sa = sb + (kt % 3) * STAGE2_B, sbf = sa + TILE_128;
#pragma unroll
        for (int kk = 0; kk < 2; kk++) {
            uint32_t aF[2][4], bF[8][2];
            ldsm4(aF[0][0], aF[0][1], aF[0][2], aF[0][3], sa + aoff[0][kk]);
            ldsm4(aF[1][0], aF[1][1], aF[1][2], aF[1][3], sa + aoff[1][kk]);
#pragma unroll
            for (int j = 0; j < 4; j++)
                ldsm4(bF[2 * j][0], bF[2 * j][1], bF[2 * j + 1][0], bF[2 * j + 1][1],
                      sbf + boff[j][kk]);
#pragma unroll
            for (int i = 0; i < 2; i++)
#pragma unroll
                for (int j = 0; j < 8; j++)
                    mma16816(acc[i][j], aF[i], bF[j]);
        }
    }

    const int er = lane >> 2, ec = (lane & 3) * 2;
#pragma unroll
    for (int i = 0; i < 2; i++) {
#pragma unroll
        for (int j = 0; j < 8; j++) {
            float* p0 = C + (size_t)(wm + i * 16 + er) * NTOT + wn + j * 8 + ec;
            float* p1 = p0 + (size_t)8 * NTOT;
            *(float2*)p0 = make_float2(acc[i][j][0], acc[i][j][1]);
            *(float2*)p1 = make_float2(acc[i][j][2], acc[i][j][3]);
        }
    }
}

// ---------------- scatter back: out[t] = sum_k scale * y[e, pos] ----------------
__global__ void scatter_kernel(float* __restrict__ out) {
    const int t = blockIdx.x;
    const int tid = threadIdx.x;  // 256, one float4 each
    float4 acc = make_float4(0.f, 0.f, 0.f, 0.f);
#pragma unroll
    for (int k = 0; k < 2; k++) {
        int f = 2 * t + k;
        int pos = g_assign_pos[f];
        if (pos >= 0) {
            int e = g_flat_sel[f];
            float s = g_flat_scale[f];
            float4 v = ((const float4*)(g_ybuf + (size_t)(e * CAP + pos) * HID))[tid];
            acc.x += s * v.x; acc.y += s * v.y; acc.z += s * v.z; acc.w += s * v.w;
        }
    }
    ((float4*)(out + (size_t)t * HID))[tid] = acc;
}

// ---------------- launch ----------------
extern "C" void kernel_launch(void* const* d_in, const int* in_sizes, int n_in,
                              void* d_out, int out_size) {
    const float* hidden = (const float*)d_in[0];
    const float* logits = (const float*)d_in[1];
    const float* w31    = (const float*)d_in[2];
    const float* w2     = (const float*)d_in[3];
    float* out = (float*)d_out;

    static int smem_set = 0;
    if (!smem_set) {
        cudaFuncSetAttribute(gemm1_fused,
                             cudaFuncAttributeMaxDynamicSharedMemorySize, SMEM1);
        cudaFuncSetAttribute(gemm2_kernel,
                             cudaFuncAttributeMaxDynamicSharedMemorySize, SMEM2);
        smem_set = 1;
    }

    routing_kernel<<<1, 512>>>(logits);
    gather_kernel<<<NEXP * CAP, 256>>>(hidden);
    wcvt_kernel<<<4096, 256>>>(w31, 0, NEXP * 2 * IDIM * HID / 4);
    wcvt_kernel<<<4096, 256>>>(w2, 1, NEXP * HID * IDIM / 4);
    gemm1_fused<<<dim3(IDIM / 128, 6, NEXP), 512, SMEM1>>>();
    gemm2_kernel<<<dim3(HID / 128, 6, NEXP), 256, SMEM2>>>();
    scatter_kernel<<<NTOK, 256>>>(out);
}

// round 13
// speedup vs baseline: 1.1394x; 1.0240x over previous
#include <cuda_runtime.h>
#include <cuda_fp16.h>
#include <cstdint>

#define NTOK  4096
#define HID   1024
#define NEXP  16
#define IDIM  2048
#define CAP   768
#define NFLAT (NTOK * 2)

// ---------------- device scratch (no allocs allowed) ----------------
__device__ int   g_flat_sel[NFLAT];
__device__ float g_flat_scale[NFLAT];
__device__ int   g_assign_pos[NFLAT];
__device__ int   g_expert_count[NEXP];
__device__ int   g_expert_tok[NEXP * CAP];

__device__ __align__(256) __half g_x1[(size_t)NEXP * CAP * HID];          // A1 fp16
__device__ __align__(256) __half g_i2[(size_t)NEXP * CAP * IDIM];         // inter fp16
__device__ __align__(256) __half g_w31[(size_t)NEXP * 2 * IDIM * HID];    // B1 fp16, g3/g1 row-interleaved
__device__ __align__(256) __half g_w2[(size_t)NEXP * HID * IDIM];         // B2 fp16
__device__ __align__(256) float g_ybuf[(size_t)NEXP * CAP * HID];

// ---------------- helpers ----------------
__device__ __forceinline__ uint32_t smem_u32(const void* p) {
    uint32_t a;
    asm("{ .reg .u64 t; cvta.to.shared.u64 t, %1; cvt.u32.u64 %0, t; }" : "=r"(a) : "l"(p));
    return a;
}
__device__ __forceinline__ void cpa16(uint32_t s, const void* g) {
    asm volatile("cp.async.cg.shared.global [%0], [%1], 16;" :: "r"(s), "l"(g) : "memory");
}
__device__ __forceinline__ void ldsm4(uint32_t& r0, uint32_t& r1, uint32_t& r2, uint32_t& r3,
                                      uint32_t addr) {
    asm volatile("ldmatrix.sync.aligned.m8n8.x4.shared.b16 {%0,%1,%2,%3}, [%4];"
                 : "=r"(r0), "=r"(r1), "=r"(r2), "=r"(r3) : "r"(addr));
}
__device__ __forceinline__ void mma16816(float* c, const uint32_t* a, const uint32_t* b) {
    asm volatile(
        "mma.sync.aligned.m16n8k16.row.col.f32.f16.f16.f32 "
        "{%0,%1,%2,%3}, {%4,%5,%6,%7}, {%8,%9}, {%0,%1,%2,%3};"
        : "+f"(c[0]), "+f"(c[1]), "+f"(c[2]), "+f"(c[3])
        : "r"(a[0]), "r"(a[1]), "r"(a[2]), "r"(a[3]), "r"(b[0]), "r"(b[1]));
}
__device__ __forceinline__ uint32_t pack2h(__half a, __half b) {
    __half2 t(a, b);
    return *reinterpret_cast<uint32_t*>(&t);
}
__device__ __forceinline__ float silu_f(float v) {
    return v / (1.f + __expf(-v));
}
// padded smem tile: 128 rows x 32 fp16 (64B data), row stride 80B -> conflict-free
#define ROW_B 80
#define TILE_B (128 * ROW_B)          // 10240 bytes per operand tile
#define STAGE_B (2 * TILE_B)          // 20480: A | B
#define NSTAGE 3
#define SMEM_BYTES (NSTAGE * STAGE_B) // 61440

// ---------------- routing: softmax top-2 + capacity positions ----------------
__global__ void routing_kernel(const float* __restrict__ logits) {
    __shared__ unsigned char sh_sel[NFLAT];
    const int tid = threadIdx.x;  // 512 threads = 16 warps

    for (int t = tid; t < NTOK; t += 512) {
        const float* l = logits + t * NEXP;
        float l1 = -1e30f, l2 = -1e30f;
        int i1 = 0, i2 = 0;
#pragma unroll
        for (int j = 0; j < NEXP; j++) {
            float v = l[j];
            if (v > l1)      { l2 = l1; i2 = i1; l1 = v; i1 = j; }
            else if (v > l2) { l2 = v; i2 = j; }
        }
        float e2 = __expf(l2 - l1);
        float s1 = 1.f / (1.f + e2);
        g_flat_sel[2 * t]     = i1;
        g_flat_sel[2 * t + 1] = i2;
        g_flat_scale[2 * t]     = s1;
        g_flat_scale[2 * t + 1] = 1.f - s1;
        sh_sel[2 * t]     = (unsigned char)i1;
        sh_sel[2 * t + 1] = (unsigned char)i2;
    }
    __syncthreads();

    const int w = tid >> 5, lane = tid & 31;
    int base = 0;
    for (int c = 0; c < NFLAT; c += 32) {
        int s = sh_sel[c + lane];
        unsigned m = __ballot_sync(0xffffffffu, s == w);
        if (s == w) {
            int pos = base + __popc(m & ((1u << lane) - 1u));
            g_assign_pos[c + lane] = (pos < CAP) ? pos : -1;
            if (pos < CAP) g_expert_tok[w * CAP + pos] = (c + lane) >> 1;
        }
        base += __popc(m);
    }
    if (lane == 0) g_expert_count[w] = base < CAP ? base : CAP;
}

// ---------------- weight convert: f32 -> fp16 (device-resolved dst) ----------------
// which==0: w31 with g3/g1 ROW INTERLEAVING per expert:
//   dst row r (r in [0,4096) within expert) <- src row (r>>1) + (r&1)*IDIM.
//   Even rows = g3 (w31[0:IDIM)), odd rows = g1 (w31[IDIM:2*IDIM)).
// which==1: w2 straight convert.
__global__ void wcvt_kernel(const float* __restrict__ src, int which, int n4) {
    int stride = gridDim.x * blockDim.x;
    if (which) {
        for (int i = blockIdx.x * blockDim.x + threadIdx.x; i < n4; i += stride) {
            float4 v = ((const float4*)src)[i];
            ((uint2*)g_w2)[i] = make_uint2(
                pack2h(__float2half_rn(v.x), __float2half_rn(v.y)),
                pack2h(__float2half_rn(v.z), __float2half_rn(v.w)));
        }
    } else {
        constexpr int K4 = HID / 4;               // 256 float4 per row
        constexpr int ROWS_E = 2 * IDIM;          // 4096 rows per expert
        for (int i = blockIdx.x * blockDim.x + threadIdx.x; i < n4; i += stride) {
            int drow = i / K4, c4 = i - drow * K4;
            int e = drow / ROWS_E, r = drow - e * ROWS_E;
            int srow = e * ROWS_E + (r >> 1) + (r & 1) * IDIM;
            float4 v = ((const float4*)src)[(size_t)srow * K4 + c4];
            ((uint2*)g_w31)[i] = make_uint2(
                pack2h(__float2half_rn(v.x), __float2half_rn(v.y)),
                pack2h(__float2half_rn(v.z), __float2half_rn(v.w)));
        }
    }
}

// ---------------- gather rows into contiguous fp16 buffer ----------------
__global__ void gather_kernel(const float* __restrict__ hidden) {
    const int row = blockIdx.x;            // [0, NEXP*CAP)
    const int e = row / CAP, p = row % CAP;
    const int t = threadIdx.x;             // 256, one float4 each
    float4 v = make_float4(0.f, 0.f, 0.f, 0.f);
    if (p < g_expert_count[e]) {
        int tok = g_expert_tok[row];
        v = ((const float4*)(hidden + (size_t)tok * HID))[t];
    }
    *(uint2*)(g_x1 + (size_t)row * HID + t * 4) = make_uint2(
        pack2h(__float2half_rn(v.x), __float2half_rn(v.y)),
        pack2h(__float2half_rn(v.z), __float2half_rn(v.w)));
}

// ---------------- fp16 HMMA GEMM (R10 shape), optional fused SiLU epilogue ----------------
// CTA tile 128x128 (B-rows), warp tile 32x64, BK=32, 3-stage cp.async, 256 thr, 2 CTA/SM.
// FIRST: B = interleaved w31; thread accumulator cols (ec, ec+1) = (g3, g1) of ONE
// inter-column -> epilogue computes g3*silu(g1) in registers, writes fp16 g_i2.
template<int NTOT, int K, bool FIRST>
__global__ __launch_bounds__(256, 2) void hmma_gemm() {
    const int e = blockIdx.z;
    if ((int)(blockIdx.y * 128) >= g_expert_count[e]) return;

    extern __shared__ __align__(128) char smem[];
    const uint32_t sb = smem_u32(smem);

    const size_t rowbase = (size_t)e * CAP + (size_t)blockIdx.y * 128;
    const __half* A = (FIRST ? g_x1 : g_i2) + rowbase * K;
    const __half* B = (FIRST ? g_w31 : g_w2)
        + ((size_t)e * NTOT + (size_t)blockIdx.x * 128) * K;

    const int tid = threadIdx.x, lane = tid & 31, warp = tid >> 5;
    const int wm = (warp & 3) * 32, wn = (warp >> 2) * 64;

    // cp.async load map: rows (tid>>2), (tid>>2)+64, 16B chunk (tid&3)
    const int lrow0 = tid >> 2, lc0 = tid & 3;
    const int lrow1 = lrow0 + 64;
    const uint32_t s0 = (uint32_t)(lrow0 * ROW_B + lc0 * 16);
    const uint32_t s1 = (uint32_t)(lrow1 * ROW_B + lc0 * 16);
    const size_t ga0 = (size_t)lrow0 * K + lc0 * 8;
    const size_t ga1 = (size_t)lrow1 * K + lc0 * 8;

    // ldmatrix per-lane offsets (verified coordinates R7-R12)
    uint32_t aoff[2][2], boff[4][2];
    {
        const int am = lane & 15, ah = lane >> 4;
        const int mt = lane >> 3;
        const int bn = ((mt >> 1) << 3) + (lane & 7), bh = mt & 1;
#pragma unroll
        for (int i = 0; i < 2; i++)
#pragma unroll
            for (int kk = 0; kk < 2; kk++)
                aoff[i][kk] = (uint32_t)((wm + i * 16 + am) * ROW_B + (kk * 2 + ah) * 16);
#pragma unroll
        for (int j = 0; j < 4; j++)
#pragma unroll
            for (int kk = 0; kk < 2; kk++)
                boff[j][kk] = (uint32_t)((wn + j * 16 + bn) * ROW_B + (kk * 2 + bh) * 16);
    }

    float acc[2][8][4];
#pragma unroll
    for (int i = 0; i < 2; i++)
#pragma unroll
        for (int j = 0; j < 8; j++)
#pragma unroll
            for (int q = 0; q < 4; q++) acc[i][j][q] = 0.f;

    constexpr int NK = K / 32;

    auto load_stage = [&](int kt) {
        const int kl = kt * 32;
        const uint32_t sa = sb + (kt % NSTAGE) * STAGE_B;
        cpa16(sa + s0, A + ga0 + kl);
        cpa16(sa + s1, A + ga1 + kl);
        cpa16(sa + TILE_B + s0, B + ga0 + kl);
        cpa16(sa + TILE_B + s1, B + ga1 + kl);
    };

    load_stage(0);
    asm volatile("cp.async.commit_group;" ::: "memory");
    load_stage(1);
    asm volatile("cp.async.commit_group;" ::: "memory");

    for (int kt = 0; kt < NK; kt++) {
        asm volatile("cp.async.wait_group 1;" ::: "memory");
        __syncthreads();
        if (kt + 2 < NK) load_stage(kt + 2);
        asm volatile("cp.async.commit_group;" ::: "memory");

        const uint32_t sa = sb + (kt % NSTAGE) * STAGE_B, sbf = sa + TILE_B;
#pragma unroll
        for (int kk = 0; kk < 2; kk++) {
            uint32_t aF[2][4], bF[8][2];
            ldsm4(aF[0][0], aF[0][1], aF[0][2], aF[0][3], sa + aoff[0][kk]);
            ldsm4(aF[1][0], aF[1][1], aF[1][2], aF[1][3], sa + aoff[1][kk]);
#pragma unroll
            for (int j = 0; j < 4; j++)
                ldsm4(bF[2 * j][0], bF[2 * j][1], bF[2 * j + 1][0], bF[2 * j + 1][1],
                      sbf + boff[j][kk]);
#pragma unroll
            for (int i = 0; i < 2; i++)
#pragma unroll
                for (int j = 0; j < 8; j++)
                    mma16816(acc[i][j], aF[i], bF[j]);
        }
    }

    const int er = lane >> 2, ec = (lane & 3) * 2;
    if (FIRST) {
        // fused epilogue: col pair (ec,ec+1) = (g3, g1) of inter col; write fp16
        const int icol0 = blockIdx.x * 64 + wn / 2 + (lane & 3);  // + j*4
#pragma unroll
        for (int i = 0; i < 2; i++) {
            const size_t r0 = rowbase + wm + i * 16 + er;
#pragma unroll
            for (int j = 0; j < 8; j++) {
                const int icol = icol0 + j * 4;
                float v0 = acc[i][j][0] * silu_f(acc[i][j][1]);
                float v1 = acc[i][j][2] * silu_f(acc[i][j][3]);
                *(__half*)(g_i2 + r0 * IDIM + icol) = __float2half_rn(v0);
                *(__half*)(g_i2 + (r0 + 8) * IDIM + icol) = __float2half_rn(v1);
            }
        }
    } else {
        float* C = g_ybuf + rowbase * NTOT + (size_t)blockIdx.x * 128;
#pragma unroll
        for (int i = 0; i < 2; i++) {
#pragma unroll
            for (int j = 0; j < 8; j++) {
                float* p0 = C + (size_t)(wm + i * 16 + er) * NTOT + wn + j * 8 + ec;
                float* p1 = p0 + (size_t)8 * NTOT;
                *(float2*)p0 = make_float2(acc[i][j][0], acc[i][j][1]);
                *(float2*)p1 = make_float2(acc[i][j][2], acc[i][j][3]);
            }
        }
    }
}

// ---------------- scatter back: out[t] = sum_k scale * y[e, pos] ----------------
__global__ void scatter_kernel(float* __restrict__ out) {
    const int t = blockIdx.x;
    const int tid = threadIdx.x;  // 256, one float4 each
    float4 acc = make_float4(0.f, 0.f, 0.f, 0.f);
#pragma unroll
    for (int k = 0; k < 2; k++) {
        int f = 2 * t + k;
        int pos = g_assign_pos[f];
        if (pos >= 0) {
            int e = g_flat_sel[f];
            float s = g_flat_scale[f];
            float4 v = ((const float4*)(g_ybuf + (size_t)(e * CAP + pos) * HID))[tid];
            acc.x += s * v.x; acc.y += s * v.y; acc.z += s * v.z; acc.w += s * v.w;
        }
    }
    ((float4*)(out + (size_t)t * HID))[tid] = acc;
}

// ---------------- launch ----------------
extern "C" void kernel_launch(void* const* d_in, const int* in_sizes, int n_in,
                              void* d_out, int out_size) {
    const float* hidden = (const float*)d_in[0];
    const float* logits = (const float*)d_in[1];
    const float* w31    = (const float*)d_in[2];
    const float* w2     = (const float*)d_in[3];
    float* out = (float*)d_out;

    static int smem_set = 0;
    if (!smem_set) {
        cudaFuncSetAttribute(hmma_gemm<2 * IDIM, HID, true>,
                             cudaFuncAttributeMaxDynamicSharedMemorySize, SMEM_BYTES);
        cudaFuncSetAttribute(hmma_gemm<HID, IDIM, false>,
                             cudaFuncAttributeMaxDynamicSharedMemorySize, SMEM_BYTES);
        smem_set = 1;
    }

    routing_kernel<<<1, 512>>>(logits);
    gather_kernel<<<NEXP * CAP, 256>>>(hidden);
    wcvt_kernel<<<4096, 256>>>(w31, 0, NEXP * 2 * IDIM * HID / 4);
    wcvt_kernel<<<4096, 256>>>(w2, 1, NEXP * HID * IDIM / 4);
    hmma_gemm<2 * IDIM, HID, true><<<dim3(32, 6, NEXP), 256, SMEM_BYTES>>>();
    hmma_gemm<HID, IDIM, false><<<dim3(8, 6, NEXP), 256, SMEM_BYTES>>>();
    scatter_kernel<<<NTOK, 256>>>(out);
}

// round 14
// speedup vs baseline: 1.1511x; 1.0103x over previous
#include <cuda_runtime.h>
#include <cuda_fp16.h>
#include <cstdint>

#define NTOK  4096
#define HID   1024
#define NEXP  16
#define IDIM  2048
#define CAP   768
#define NFLAT (NTOK * 2)

// ---------------- device scratch (no allocs allowed) ----------------
__device__ int   g_flat_sel[NFLAT];
__device__ float g_flat_scale[NFLAT];
__device__ int   g_assign_pos[NFLAT];
__device__ int   g_expert_count[NEXP];
__device__ int   g_expert_tok[NEXP * CAP];

__device__ __align__(256) __half g_x1[(size_t)NEXP * CAP * HID];          // A1 fp16
__device__ __align__(256) __half g_i2[(size_t)NEXP * CAP * IDIM];         // inter fp16
__device__ __align__(256) __half g_w31[(size_t)NEXP * 2 * IDIM * HID];    // B1 fp16, g3/g1 row-interleaved
__device__ __align__(256) __half g_w2[(size_t)NEXP * HID * IDIM];         // B2 fp16
__device__ __align__(256) float g_ybuf[(size_t)NEXP * CAP * HID];

// ---------------- helpers ----------------
__device__ __forceinline__ uint32_t smem_u32(const void* p) {
    uint32_t a;
    asm("{ .reg .u64 t; cvta.to.shared.u64 t, %1; cvt.u32.u64 %0, t; }" : "=r"(a) : "l"(p));
    return a;
}
__device__ __forceinline__ void cpa16(uint32_t s, const void* g) {
    asm volatile("cp.async.cg.shared.global [%0], [%1], 16;" :: "r"(s), "l"(g) : "memory");
}
__device__ __forceinline__ void ldsm4(uint32_t& r0, uint32_t& r1, uint32_t& r2, uint32_t& r3,
                                      uint32_t addr) {
    asm volatile("ldmatrix.sync.aligned.m8n8.x4.shared.b16 {%0,%1,%2,%3}, [%4];"
                 : "=r"(r0), "=r"(r1), "=r"(r2), "=r"(r3) : "r"(addr));
}
__device__ __forceinline__ void mma16816(float* c, const uint32_t* a, const uint32_t* b) {
    asm volatile(
        "mma.sync.aligned.m16n8k16.row.col.f32.f16.f16.f32 "
        "{%0,%1,%2,%3}, {%4,%5,%6,%7}, {%8,%9}, {%0,%1,%2,%3};"
        : "+f"(c[0]), "+f"(c[1]), "+f"(c[2]), "+f"(c[3])
        : "r"(a[0]), "r"(a[1]), "r"(a[2]), "r"(a[3]), "r"(b[0]), "r"(b[1]));
}
__device__ __forceinline__ uint32_t pack2h(__half a, __half b) {
    __half2 t(a, b);
    return *reinterpret_cast<uint32_t*>(&t);
}
__device__ __forceinline__ float silu_f(float v) {
    return v / (1.f + __expf(-v));
}
// padded smem tile: 128 rows x 32 fp16 (64B data), row stride 80B -> conflict-free
#define ROW_B 80
#define TILE_B (128 * ROW_B)          // 10240 bytes per operand tile
#define STAGE_B (2 * TILE_B)          // 20480: A | B
#define NSTAGE 3
#define SMEM_BYTES (NSTAGE * STAGE_B) // 61440
// epilogue staging tile (GEMM1): 128 rows x 64 fp16, row stride 144B (18432 B <= STAGE_B)
#define EPI_ROW_B 144

// ---------------- routing: softmax top-2 + capacity positions ----------------
__global__ void routing_kernel(const float* __restrict__ logits) {
    __shared__ unsigned char sh_sel[NFLAT];
    const int tid = threadIdx.x;  // 512 threads = 16 warps

    for (int t = tid; t < NTOK; t += 512) {
        const float* l = logits + t * NEXP;
        float l1 = -1e30f, l2 = -1e30f;
        int i1 = 0, i2 = 0;
#pragma unroll
        for (int j = 0; j < NEXP; j++) {
            float v = l[j];
            if (v > l1)      { l2 = l1; i2 = i1; l1 = v; i1 = j; }
            else if (v > l2) { l2 = v; i2 = j; }
        }
        float e2 = __expf(l2 - l1);
        float s1 = 1.f / (1.f + e2);
        g_flat_sel[2 * t]     = i1;
        g_flat_sel[2 * t + 1] = i2;
        g_flat_scale[2 * t]     = s1;
        g_flat_scale[2 * t + 1] = 1.f - s1;
        sh_sel[2 * t]     = (unsigned char)i1;
        sh_sel[2 * t + 1] = (unsigned char)i2;
    }
    __syncthreads();

    const int w = tid >> 5, lane = tid & 31;
    int base = 0;
    for (int c = 0; c < NFLAT; c += 32) {
        int s = sh_sel[c + lane];
        unsigned m = __ballot_sync(0xffffffffu, s == w);
        if (s == w) {
            int pos = base + __popc(m & ((1u << lane) - 1u));
            g_assign_pos[c + lane] = (pos < CAP) ? pos : -1;
            if (pos < CAP) g_expert_tok[w * CAP + pos] = (c + lane) >> 1;
        }
        base += __popc(m);
    }
    if (lane == 0) g_expert_count[w] = base < CAP ? base : CAP;
}

// ---------------- weight convert: f32 -> fp16 (device-resolved dst) ----------------
// which==0: w31 with g3/g1 ROW INTERLEAVING per expert (even rows g3, odd rows g1).
// which==1: w2 straight convert.
__global__ void wcvt_kernel(const float* __restrict__ src, int which, int n4) {
    int stride = gridDim.x * blockDim.x;
    if (which) {
        for (int i = blockIdx.x * blockDim.x + threadIdx.x; i < n4; i += stride) {
            float4 v = ((const float4*)src)[i];
            ((uint2*)g_w2)[i] = make_uint2(
                pack2h(__float2half_rn(v.x), __float2half_rn(v.y)),
                pack2h(__float2half_rn(v.z), __float2half_rn(v.w)));
        }
    } else {
        constexpr int K4 = HID / 4;               // 256 float4 per row
        constexpr int ROWS_E = 2 * IDIM;          // 4096 rows per expert
        for (int i = blockIdx.x * blockDim.x + threadIdx.x; i < n4; i += stride) {
            int drow = i / K4, c4 = i - drow * K4;
            int e = drow / ROWS_E, r = drow - e * ROWS_E;
            int srow = e * ROWS_E + (r >> 1) + (r & 1) * IDIM;
            float4 v = ((const float4*)src)[(size_t)srow * K4 + c4];
            ((uint2*)g_w31)[i] = make_uint2(
                pack2h(__float2half_rn(v.x), __float2half_rn(v.y)),
                pack2h(__float2half_rn(v.z), __float2half_rn(v.w)));
        }
    }
}

// ---------------- gather rows into contiguous fp16 buffer ----------------
__global__ void gather_kernel(const float* __restrict__ hidden) {
    const int row = blockIdx.x;            // [0, NEXP*CAP)
    const int e = row / CAP, p = row % CAP;
    const int t = threadIdx.x;             // 256, one float4 each
    float4 v = make_float4(0.f, 0.f, 0.f, 0.f);
    if (p < g_expert_count[e]) {
        int tok = g_expert_tok[row];
        v = ((const float4*)(hidden + (size_t)tok * HID))[t];
    }
    *(uint2*)(g_x1 + (size_t)row * HID + t * 4) = make_uint2(
        pack2h(__float2half_rn(v.x), __float2half_rn(v.y)),
        pack2h(__float2half_rn(v.z), __float2half_rn(v.w)));
}

// ---------------- fp16 HMMA GEMM (R10 shape), fused SiLU epilogue via smem staging ----------------
// CTA tile 128x128 (B-rows), warp tile 32x64, BK=32, 3-stage cp.async, 256 thr, 2 CTA/SM.
// FIRST: B = interleaved w31; acc col pair (ec,ec+1) = (g3, g1) of ONE inter col.
// Epilogue stages the 128x64 fp16 inter tile in smem, then stores coalesced uint4.
template<int NTOT, int K, bool FIRST>
__global__ __launch_bounds__(256, 2) void hmma_gemm() {
    const int e = blockIdx.z;
    if ((int)(blockIdx.y * 128) >= g_expert_count[e]) return;

    extern __shared__ __align__(128) char smem[];
    const uint32_t sb = smem_u32(smem);

    const size_t rowbase = (size_t)e * CAP + (size_t)blockIdx.y * 128;
    const __half* A = (FIRST ? g_x1 : g_i2) + rowbase * K;
    const __half* B = (FIRST ? g_w31 : g_w2)
        + ((size_t)e * NTOT + (size_t)blockIdx.x * 128) * K;

    const int tid = threadIdx.x, lane = tid & 31, warp = tid >> 5;
    const int wm = (warp & 3) * 32, wn = (warp >> 2) * 64;

    // cp.async load map: rows (tid>>2), (tid>>2)+64, 16B chunk (tid&3)
    const int lrow0 = tid >> 2, lc0 = tid & 3;
    const int lrow1 = lrow0 + 64;
    const uint32_t s0 = (uint32_t)(lrow0 * ROW_B + lc0 * 16);
    const uint32_t s1 = (uint32_t)(lrow1 * ROW_B + lc0 * 16);
    const size_t ga0 = (size_t)lrow0 * K + lc0 * 8;
    const size_t ga1 = (size_t)lrow1 * K + lc0 * 8;

    // ldmatrix per-lane offsets (verified coordinates R7-R13)
    uint32_t aoff[2][2], boff[4][2];
    {
        const int am = lane & 15, ah = lane >> 4;
        const int mt = lane >> 3;
        const int bn = ((mt >> 1) << 3) + (lane & 7), bh = mt & 1;
#pragma unroll
        for (int i = 0; i < 2; i++)
#pragma unroll
            for (int kk = 0; kk < 2; kk++)
                aoff[i][kk] = (uint32_t)((wm + i * 16 + am) * ROW_B + (kk * 2 + ah) * 16);
#pragma unroll
        for (int j = 0; j < 4; j++)
#pragma unroll
            for (int kk = 0; kk < 2; kk++)
                boff[j][kk] = (uint32_t)((wn + j * 16 + bn) * ROW_B + (kk * 2 + bh) * 16);
    }

    float acc[2][8][4];
#pragma unroll
    for (int i = 0; i < 2; i++)
#pragma unroll
        for (int j = 0; j < 8; j++)
#pragma unroll
            for (int q = 0; q < 4; q++) acc[i][j][q] = 0.f;

    constexpr int NK = K / 32;

    auto load_stage = [&](int kt) {
        const int kl = kt * 32;
        const uint32_t sa = sb + (kt % NSTAGE) * STAGE_B;
        cpa16(sa + s0, A + ga0 + kl);
        cpa16(sa + s1, A + ga1 + kl);
        cpa16(sa + TILE_B + s0, B + ga0 + kl);
        cpa16(sa + TILE_B + s1, B + ga1 + kl);
    };

    load_stage(0);
    asm volatile("cp.async.commit_group;" ::: "memory");
    load_stage(1);
    asm volatile("cp.async.commit_group;" ::: "memory");

    for (int kt = 0; kt < NK; kt++) {
        asm volatile("cp.async.wait_group 1;" ::: "memory");
        __syncthreads();
        if (kt + 2 < NK) load_stage(kt + 2);
        asm volatile("cp.async.commit_group;" ::: "memory");

        const uint32_t sa = sb + (kt % NSTAGE) * STAGE_B, sbf = sa + TILE_B;
#pragma unroll
        for (int kk = 0; kk < 2; kk++) {
            uint32_t aF[2][4], bF[8][2];
            ldsm4(aF[0][0], aF[0][1], aF[0][2], aF[0][3], sa + aoff[0][kk]);
            ldsm4(aF[1][0], aF[1][1], aF[1][2], aF[1][3], sa + aoff[1][kk]);
#pragma unroll
            for (int j = 0; j < 4; j++)
                ldsm4(bF[2 * j][0], bF[2 * j][1], bF[2 * j + 1][0], bF[2 * j + 1][1],
                      sbf + boff[j][kk]);
#pragma unroll
            for (int i = 0; i < 2; i++)
#pragma unroll
                for (int j = 0; j < 8; j++)
                    mma16816(acc[i][j], aF[i], bF[j]);
        }
    }

    const int er = lane >> 2, ec = (lane & 3) * 2;
    if (FIRST) {
        // ---- fused SiLU epilogue with smem staging (reuse pipeline buffers) ----
        asm volatile("cp.async.wait_group 0;" ::: "memory");
        __syncthreads();                       // all mainloop smem reads done
        // stage: 128 rows x 64 fp16, row stride EPI_ROW_B
        const int lcolL = wn / 2 + (lane & 3); // local inter col, + j*4
#pragma unroll
        for (int i = 0; i < 2; i++) {
            const int r0 = wm + i * 16 + er;
#pragma unroll
            for (int j = 0; j < 8; j++) {
                const int c = lcolL + j * 4;
                float v0 = acc[i][j][0] * silu_f(acc[i][j][1]);
                float v1 = acc[i][j][2] * silu_f(acc[i][j][3]);
                *(__half*)(smem + (size_t)r0 * EPI_ROW_B + c * 2) = __float2half_rn(v0);
                *(__half*)(smem + (size_t)(r0 + 8) * EPI_ROW_B + c * 2) = __float2half_rn(v1);
            }
        }
        __syncthreads();
        // coalesced copy out: 128 rows x 128B (8 x uint4 per row)
        __half* dst = g_i2 + rowbase * IDIM + (size_t)blockIdx.x * 64;
#pragma unroll
        for (int it = 0; it < 4; it++) {
            const int idx = tid + it * 256;
            const int r = idx >> 3, c = idx & 7;
            uint4 v = *(const uint4*)(smem + (size_t)r * EPI_ROW_B + c * 16);
            *(uint4*)(dst + (size_t)r * IDIM + c * 8) = v;
        }
    } else {
        float* C = g_ybuf + rowbase * NTOT + (size_t)blockIdx.x * 128;
#pragma unroll
        for (int i = 0; i < 2; i++) {
#pragma unroll
            for (int j = 0; j < 8; j++) {
                float* p0 = C + (size_t)(wm + i * 16 + er) * NTOT + wn + j * 8 + ec;
                float* p1 = p0 + (size_t)8 * NTOT;
                *(float2*)p0 = make_float2(acc[i][j][0], acc[i][j][1]);
                *(float2*)p1 = make_float2(acc[i][j][2], acc[i][j][3]);
            }
        }
    }
}

// ---------------- scatter back: out[t] = sum_k scale * y[e, pos] ----------------
__global__ void scatter_kernel(float* __restrict__ out) {
    const int t = blockIdx.x;
    const int tid = threadIdx.x;  // 256, one float4 each
    float4 acc = make_float4(0.f, 0.f, 0.f, 0.f);
#pragma unroll
    for (int k = 0; k < 2; k++) {
        int f = 2 * t + k;
        int pos = g_assign_pos[f];
        if (pos >= 0) {
            int e = g_flat_sel[f];
            float s = g_flat_scale[f];
            float4 v = ((const float4*)(g_ybuf + (size_t)(e * CAP + pos) * HID))[tid];
            acc.x += s * v.x; acc.y += s * v.y; acc.z += s * v.z; acc.w += s * v.w;
        }
    }
    ((float4*)(out + (size_t)t * HID))[tid] = acc;
}

// ---------------- launch ----------------
extern "C" void kernel_launch(void* const* d_in, const int* in_sizes, int n_in,
                              void* d_out, int out_size) {
    const float* hidden = (const float*)d_in[0];
    const float* logits = (const float*)d_in[1];
    const float* w31    = (const float*)d_in[2];
    const float* w2     = (const float*)d_in[3];
    float* out = (float*)d_out;

    static int smem_set = 0;
    if (!smem_set) {
        cudaFuncSetAttribute(hmma_gemm<2 * IDIM, HID, true>,
                             cudaFuncAttributeMaxDynamicSharedMemorySize, SMEM_BYTES);
        cudaFuncSetAttribute(hmma_gemm<HID, IDIM, false>,
                             cudaFuncAttributeMaxDynamicSharedMemorySize, SMEM_BYTES);
        smem_set = 1;
    }

    routing_kernel<<<1, 512>>>(logits);
    gather_kernel<<<NEXP * CAP, 256>>>(hidden);
    wcvt_kernel<<<4096, 256>>>(w31, 0, NEXP * 2 * IDIM * HID / 4);
    wcvt_kernel<<<4096, 256>>>(w2, 1, NEXP * HID * IDIM / 4);
    hmma_gemm<2 * IDIM, HID, true><<<dim3(32, 6, NEXP), 256, SMEM_BYTES>>>();
    hmma_gemm<HID, IDIM, false><<<dim3(8, 6, NEXP), 256, SMEM_BYTES>>>();
    scatter_kernel<<<NTOK, 256>>>(out);
}